// round 1
// baseline (speedup 1.0000x reference)
#include <cuda_runtime.h>
#include <cuda_bf16.h>
#include <math.h>

// ---------------- problem constants ----------------
#define NG        50
#define KNB       32
#define NUM_G     64
#define ATOMS     128
#define NTOT      (NUM_G * ATOMS)     // 8192
#define HID       128
#define FIL       128
#define LAYERS    6
#define EDGES     (NTOT * KNB)        // 262144
#define CUTOFF    10.0f
#define PI_C      3.14159265f

#define INVALID_KEY 0xFFFFFFFFFFFFFFFFULL

// ---------------- device scratch ----------------
__device__ int   g_idx [EDGES];
__device__ float g_dist[EDGES];
__device__ float g_cval[EDGES];
__device__ float g_rbf [EDGES * NG];     // ~52 MB
__device__ float g_h   [NTOT * HID];
__device__ float g_x1  [NTOT * FIL];
__device__ float g_agg [NTOT * FIL];

__device__ __forceinline__ float silu_f(float v) {
    return v / (1.0f + __expf(-v));
}

// ---------------- graph build: per-node 32-NN, tie-break by index ----------------
__global__ void build_graph_kernel(const float* __restrict__ pos,
                                   const int* __restrict__ batch)
{
    const int i = blockIdx.x;          // center node
    const int t = threadIdx.x;         // candidate slot within graph (128)
    const int base = (i >> 7) << 7;    // graph start
    const int j = base + t;

    __shared__ unsigned long long key[ATOMS];
    __shared__ unsigned long long red[ATOMS];

    const float px = pos[3*i], py = pos[3*i+1], pz = pos[3*i+2];
    const float dx = pos[3*j]   - px;
    const float dy = pos[3*j+1] - py;
    const float dz = pos[3*j+2] - pz;
    const float d2 = dx*dx + dy*dy + dz*dz;
    const bool valid = (j != i) && (batch[j] == batch[i]) && (d2 < CUTOFF*CUTOFF);

    key[t] = valid
        ? ((((unsigned long long)__float_as_uint(d2)) << 32) | (unsigned int)j)
        : INVALID_KEY;
    __syncthreads();

    for (int k = 0; k < KNB; k++) {
        red[t] = key[t];
        __syncthreads();
        #pragma unroll
        for (int s = 64; s >= 1; s >>= 1) {
            if (t < s) {
                unsigned long long o = red[t + s];
                if (o < red[t]) red[t] = o;
            }
            __syncthreads();
        }
        const unsigned long long best = red[0];
        if (best != INVALID_KEY && key[t] == best) key[t] = INVALID_KEY;
        if (t == k) {
            const int eo = i * KNB + k;
            if (best != INVALID_KEY) {
                const int   jj = (int)(best & 0xffffffffu);
                const float d  = sqrtf(__uint_as_float((unsigned int)(best >> 32)));
                g_idx[eo]  = jj;
                g_dist[eo] = d;
                const float cv = 0.5f * (cosf(d * (PI_C / CUTOFF)) + 1.0f);
                g_cval[eo] = (d < CUTOFF) ? cv : 0.0f;
            } else {
                g_idx[eo]  = i;      // harmless target, message will be zero
                g_dist[eo] = 1.0f;   // matches reference's safe-sqrt value
                g_cval[eo] = 0.0f;
            }
        }
        __syncthreads();
    }
}

// ---------------- rbf expansion ----------------
__global__ void rbf_kernel()
{
    const int id = blockIdx.x * blockDim.x + threadIdx.x;
    if (id >= EDGES * NG) return;
    const int e = id / NG;
    const int g = id - e * NG;
    const float w = CUTOFF / (float)(NG - 1);
    const float t = (g_dist[e] - (float)g * w) / w;
    g_rbf[id] = expf(-0.5f * t * t);
}

// ---------------- embedding ----------------
__global__ void embed_kernel(const int* __restrict__ z, const float* __restrict__ emb)
{
    const int id = blockIdx.x * blockDim.x + threadIdx.x;
    if (id >= NTOT * HID) return;
    const int n = id >> 7;
    const int c = id & 127;
    g_h[id] = emb[z[n] * HID + c];
}

// ---------------- zero agg ----------------
__global__ void zero_agg_kernel()
{
    const int id = blockIdx.x * blockDim.x + threadIdx.x;
    if (id < NTOT * FIL) g_agg[id] = 0.0f;
}

// ---------------- node linear: y = x@W + b   (mode 0)
//                   or        h += silu(x@W + b)  (mode 1) ----------------
__global__ void linear_kernel(const float* __restrict__ x,
                              const float* __restrict__ W,
                              const float* __restrict__ b,
                              float* __restrict__ y,
                              int mode)
{
    __shared__ float xs[32 * 128];
    const int c  = threadIdx.x;
    const int r0 = blockIdx.x * 32;

    for (int idx = threadIdx.x; idx < 32 * 128; idx += 128)
        xs[idx] = x[r0 * 128 + idx];
    __syncthreads();

    float acc[32];
    #pragma unroll
    for (int e = 0; e < 32; e++) acc[e] = 0.0f;

    #pragma unroll 4
    for (int k = 0; k < 128; k++) {
        const float w = W[k * 128 + c];
        #pragma unroll
        for (int e = 0; e < 32; e++) acc[e] += xs[e * 128 + k] * w;
    }
    const float bias = b[c];
    if (mode == 0) {
        #pragma unroll
        for (int e = 0; e < 32; e++) y[(r0 + e) * 128 + c] = acc[e] + bias;
    } else {
        #pragma unroll
        for (int e = 0; e < 32; e++) {
            const float v = acc[e] + bias;
            y[(r0 + e) * 128 + c] += silu_f(v);
        }
    }
}

// ---------------- edge filter MLP + scatter (the hot kernel) ----------------
// persistent: weights resident in smem, grid-stride over 64-edge tiles
#define FILT_SMEM_FLOATS (6400 + 16384 + 128 + 128 + 64*50 + 64*128 + 64 + 64)

__global__ void __launch_bounds__(256, 1)
filter_kernel(const float* __restrict__ w1, const float* __restrict__ b1,
              const float* __restrict__ w2, const float* __restrict__ b2,
              int ntiles)
{
    extern __shared__ float sm[];
    float* sw1  = sm;                 // 50*128
    float* sw2  = sw1 + 6400;         // 128*128
    float* sb1  = sw2 + 16384;        // 128
    float* sb2  = sb1 + 128;          // 128
    float* srbf = sb2 + 128;          // 64*50
    float* shid = srbf + 3200;        // 64*128
    float* scv  = shid + 8192;        // 64
    int*   sdst = (int*)(scv + 64);   // 64

    const int tid  = threadIdx.x;
    const int c    = tid & 127;
    const int half = tid >> 7;

    for (int idx = tid; idx < 6400;  idx += 256) sw1[idx] = w1[idx];
    for (int idx = tid; idx < 16384; idx += 256) sw2[idx] = w2[idx];
    if (tid < 128) { sb1[tid] = b1[tid]; sb2[tid] = b2[tid]; }
    __syncthreads();

    const float bb1 = sb1[c];
    const float bb2 = sb2[c];

    for (int tile = blockIdx.x; tile < ntiles; tile += gridDim.x) {
        const int e0 = tile * 64;
        for (int idx = tid; idx < 64 * NG; idx += 256) srbf[idx] = g_rbf[e0 * NG + idx];
        if (tid < 64) { scv[tid] = g_cval[e0 + tid]; sdst[tid] = g_idx[e0 + tid]; }
        __syncthreads();

        float acc[32];
        #pragma unroll
        for (int e = 0; e < 32; e++) acc[e] = 0.0f;

        const float* rb = srbf + half * 32 * NG;
        #pragma unroll 2
        for (int g = 0; g < NG; g++) {
            const float w = sw1[g * 128 + c];
            #pragma unroll
            for (int e = 0; e < 32; e++) acc[e] += rb[e * NG + g] * w;
        }

        float* hd = shid + half * 32 * 128;
        #pragma unroll
        for (int e = 0; e < 32; e++) {
            const float v = acc[e] + bb1;
            hd[e * 128 + c] = silu_f(v);
        }
        __syncthreads();

        #pragma unroll
        for (int e = 0; e < 32; e++) acc[e] = 0.0f;

        #pragma unroll 2
        for (int k = 0; k < 128; k++) {
            const float w = sw2[k * 128 + c];
            #pragma unroll
            for (int e = 0; e < 32; e++) acc[e] += hd[e * 128 + k] * w;
        }

        #pragma unroll
        for (int e = 0; e < 32; e++) {
            const int   ee  = half * 32 + e;
            const int   ge  = e0 + ee;
            const int   src = ge >> 5;               // edge / K
            const float m   = (acc[e] + bb2) * scv[ee] * g_x1[src * 128 + c];
            atomicAdd(&g_agg[sdst[ee] * 128 + c], m);
        }
        __syncthreads();
    }
}

// ---------------- output head + per-graph sum ----------------
#define OUT_SMEM_FLOATS (128*128 + 128*65)

__global__ void out_kernel(const float* __restrict__ ow1, const float* __restrict__ ob1,
                           const float* __restrict__ ow2, const float* __restrict__ ob2,
                           float* __restrict__ out)
{
    extern __shared__ float sm[];
    float* sh = sm;            // 128*128 node features
    float* st = sh + 128*128;  // 128*65 padded hidden
    __shared__ float rsum[256];

    const int g    = blockIdx.x;
    const int tid  = threadIdx.x;
    const int base = g * ATOMS;

    for (int idx = tid; idx < 128 * 128; idx += 256)
        sh[idx] = g_h[base * 128 + idx];
    __syncthreads();

    // stage 1: hidden[n][d] = silu(h[n]@ow1 + ob1)
    const int d   = tid & 63;
    const int grp = tid >> 6;      // 0..3, 32 nodes each
    float acc[32];
    #pragma unroll
    for (int e = 0; e < 32; e++) acc[e] = 0.0f;
    const float* hh = sh + grp * 32 * 128;
    #pragma unroll 2
    for (int k = 0; k < 128; k++) {
        const float w = ow1[k * 64 + d];
        #pragma unroll
        for (int e = 0; e < 32; e++) acc[e] += hh[e * 128 + k] * w;
    }
    const float bb = ob1[d];
    #pragma unroll
    for (int e = 0; e < 32; e++) {
        const float v = acc[e] + bb;
        st[(grp * 32 + e) * 65 + d] = silu_f(v);
    }
    __syncthreads();

    // stage 2: per-node scalar, then block sum
    float o = 0.0f;
    if (tid < 128) {
        float s = ob2[0];
        #pragma unroll 4
        for (int dd = 0; dd < 64; dd++) s += st[tid * 65 + dd] * ow2[dd];
        o = s;
    }
    rsum[tid] = o;
    __syncthreads();
    for (int s = 128; s >= 1; s >>= 1) {
        if (tid < s) rsum[tid] += rsum[tid + s];
        __syncthreads();
    }
    if (tid == 0) out[g] = rsum[0];
}

// ---------------- launch ----------------
extern "C" void kernel_launch(void* const* d_in, const int* in_sizes, int n_in,
                              void* d_out, int out_size)
{
    const float* pos   = (const float*)d_in[0];
    const int*   z     = (const int*)  d_in[1];
    const int*   batch = (const int*)  d_in[2];
    const float* emb   = (const float*)d_in[3];
    const float* mw1   = (const float*)d_in[4];
    const float* mb1   = (const float*)d_in[5];
    const float* mw2   = (const float*)d_in[6];
    const float* mb2   = (const float*)d_in[7];
    const float* l1w   = (const float*)d_in[8];
    const float* l1b   = (const float*)d_in[9];
    const float* l2w   = (const float*)d_in[10];
    const float* l2b   = (const float*)d_in[11];
    const float* ow1   = (const float*)d_in[12];
    const float* ob1   = (const float*)d_in[13];
    const float* ow2   = (const float*)d_in[14];
    const float* ob2   = (const float*)d_in[15];
    float* out = (float*)d_out;

    // scratch symbol addresses (host-side, capture-safe)
    float *hp, *x1p, *aggp;
    cudaGetSymbolAddress((void**)&hp,   g_h);
    cudaGetSymbolAddress((void**)&x1p,  g_x1);
    cudaGetSymbolAddress((void**)&aggp, g_agg);

    cudaFuncSetAttribute(filter_kernel, cudaFuncAttributeMaxDynamicSharedMemorySize,
                         FILT_SMEM_FLOATS * (int)sizeof(float));
    cudaFuncSetAttribute(out_kernel, cudaFuncAttributeMaxDynamicSharedMemorySize,
                         OUT_SMEM_FLOATS * (int)sizeof(float));

    build_graph_kernel<<<NTOT, ATOMS>>>(pos, batch);
    rbf_kernel<<<(EDGES * NG + 255) / 256, 256>>>();
    embed_kernel<<<(NTOT * HID + 255) / 256, 256>>>(z, emb);

    const int ntiles = EDGES / 64;
    for (int l = 0; l < LAYERS; l++) {
        linear_kernel<<<NTOT / 32, 128>>>(hp, l1w + l * HID * FIL, l1b + l * FIL, x1p, 0);
        zero_agg_kernel<<<(NTOT * FIL + 255) / 256, 256>>>();
        filter_kernel<<<148, 256, FILT_SMEM_FLOATS * sizeof(float)>>>(
            mw1 + l * NG * FIL, mb1 + l * FIL,
            mw2 + l * FIL * FIL, mb2 + l * FIL, ntiles);
        linear_kernel<<<NTOT / 32, 128>>>(aggp, l2w + l * FIL * HID, l2b + l * HID, hp, 1);
    }

    out_kernel<<<NUM_G, 256, OUT_SMEM_FLOATS * sizeof(float)>>>(ow1, ob1, ow2, ob2, out);
}

// round 2
// speedup vs baseline: 1.4106x; 1.4106x over previous
#include <cuda_runtime.h>
#include <cuda_bf16.h>
#include <math.h>

// ---------------- problem constants ----------------
#define NG        50
#define KNB       32
#define NUM_G     64
#define ATOMS     128
#define NTOT      (NUM_G * ATOMS)     // 8192
#define HID       128
#define FIL       128
#define LAYERS    6
#define EDGES     (NTOT * KNB)        // 262144
#define CUTOFF    10.0f
#define PI_C      3.14159265f

#define INVALID_KEY 0xFFFFFFFFFFFFFFFFULL

typedef unsigned long long ull;

// ---------------- device scratch ----------------
__device__ int   g_idx [EDGES];
__device__ float g_dist[EDGES];
__device__ float g_cval[EDGES];
__device__ float g_rbf [EDGES * NG];     // layout: [tile][g][64 edges]
__device__ float g_h   [NTOT * HID];
__device__ float g_x1  [NTOT * FIL];
__device__ float g_agg [NTOT * FIL];

__device__ __forceinline__ float silu_f(float v) {
    return v / (1.0f + __expf(-v));
}

// ---------------- packed f32x2 helpers ----------------
__device__ __forceinline__ ull pack2(float x, float y) {
    ull r; asm("mov.b64 %0, {%1,%2};" : "=l"(r) : "f"(x), "f"(y)); return r;
}
__device__ __forceinline__ void unpack2(ull v, float& x, float& y) {
    asm("mov.b64 {%0,%1}, %2;" : "=f"(x), "=f"(y) : "l"(v));
}
__device__ __forceinline__ ull fma2(ull a, ull b, ull c) {
    ull d; asm("fma.rn.f32x2 %0, %1, %2, %3;" : "=l"(d) : "l"(a), "l"(b), "l"(c));
    return d;
}
__device__ __forceinline__ void red_add_v4(float* p, float a, float b, float c, float d) {
    asm volatile("red.global.add.v4.f32 [%0], {%1,%2,%3,%4};"
                 :: "l"(p), "f"(a), "f"(b), "f"(c), "f"(d) : "memory");
}

// ---------------- graph build: per-node 32-NN, tie-break by index ----------------
__global__ void build_graph_kernel(const float* __restrict__ pos,
                                   const int* __restrict__ batch)
{
    const int i = blockIdx.x;
    const int t = threadIdx.x;
    const int base = (i >> 7) << 7;
    const int j = base + t;

    __shared__ unsigned long long key[ATOMS];
    __shared__ unsigned long long red[ATOMS];

    const float px = pos[3*i], py = pos[3*i+1], pz = pos[3*i+2];
    const float dx = pos[3*j]   - px;
    const float dy = pos[3*j+1] - py;
    const float dz = pos[3*j+2] - pz;
    const float d2 = dx*dx + dy*dy + dz*dz;
    const bool valid = (j != i) && (batch[j] == batch[i]) && (d2 < CUTOFF*CUTOFF);

    key[t] = valid
        ? ((((unsigned long long)__float_as_uint(d2)) << 32) | (unsigned int)j)
        : INVALID_KEY;
    __syncthreads();

    for (int k = 0; k < KNB; k++) {
        red[t] = key[t];
        __syncthreads();
        #pragma unroll
        for (int s = 64; s >= 1; s >>= 1) {
            if (t < s) {
                unsigned long long o = red[t + s];
                if (o < red[t]) red[t] = o;
            }
            __syncthreads();
        }
        const unsigned long long best = red[0];
        if (best != INVALID_KEY && key[t] == best) key[t] = INVALID_KEY;
        if (t == k) {
            const int eo = i * KNB + k;
            if (best != INVALID_KEY) {
                const int   jj = (int)(best & 0xffffffffu);
                const float d  = sqrtf(__uint_as_float((unsigned int)(best >> 32)));
                g_idx[eo]  = jj;
                g_dist[eo] = d;
                const float cv = 0.5f * (cosf(d * (PI_C / CUTOFF)) + 1.0f);
                g_cval[eo] = (d < CUTOFF) ? cv : 0.0f;
            } else {
                g_idx[eo]  = i;
                g_dist[eo] = 1.0f;
                g_cval[eo] = 0.0f;
            }
        }
        __syncthreads();
    }
}

// ---------------- rbf expansion (transposed per-tile layout) ----------------
__global__ void rbf_kernel()
{
    const int id = blockIdx.x * blockDim.x + threadIdx.x;
    if (id >= EDGES * NG) return;
    const int tile = id / (NG * 64);
    const int r    = id - tile * (NG * 64);
    const int g    = r >> 6;
    const int e    = r & 63;
    const float w  = CUTOFF / (float)(NG - 1);
    const float t  = (g_dist[tile * 64 + e] - (float)g * w) / w;
    g_rbf[id] = expf(-0.5f * t * t);
}

// ---------------- embedding ----------------
__global__ void embed_kernel(const int* __restrict__ z, const float* __restrict__ emb)
{
    const int id = blockIdx.x * blockDim.x + threadIdx.x;
    if (id >= NTOT * HID) return;
    const int n = id >> 7;
    const int c = id & 127;
    g_h[id] = emb[z[n] * HID + c];
}

// ---------------- zero agg ----------------
__global__ void zero_agg_kernel()
{
    const int id = blockIdx.x * blockDim.x + threadIdx.x;
    if (id < NTOT * FIL) g_agg[id] = 0.0f;
}

// ---------------- node linear: y = x@W + b (mode 0) or h += silu(x@W+b) (mode 1)
__global__ void linear_kernel(const float* __restrict__ x,
                              const float* __restrict__ W,
                              const float* __restrict__ b,
                              float* __restrict__ y,
                              int mode)
{
    __shared__ float xs[128 * 34];      // transposed [k][e], pad 34
    const int c  = threadIdx.x;
    const int r0 = blockIdx.x * 32;

    #pragma unroll 4
    for (int e = 0; e < 32; e++)
        xs[c * 34 + e] = x[(r0 + e) * 128 + c];
    __syncthreads();

    ull acc[16];
    #pragma unroll
    for (int p = 0; p < 16; p++) acc[p] = 0ULL;

    #pragma unroll 4
    for (int k = 0; k < 128; k++) {
        const float w = W[k * 128 + c];
        const ull wp = pack2(w, w);
        const float* xp = &xs[k * 34];
        #pragma unroll
        for (int p = 0; p < 16; p++) {
            const ull xv = *(const ull*)(xp + 2 * p);
            acc[p] = fma2(xv, wp, acc[p]);
        }
    }
    const float bias = b[c];
    if (mode == 0) {
        #pragma unroll
        for (int p = 0; p < 16; p++) {
            float lo, hi; unpack2(acc[p], lo, hi);
            y[(r0 + 2*p)     * 128 + c] = lo + bias;
            y[(r0 + 2*p + 1) * 128 + c] = hi + bias;
        }
    } else {
        #pragma unroll
        for (int p = 0; p < 16; p++) {
            float lo, hi; unpack2(acc[p], lo, hi);
            y[(r0 + 2*p)     * 128 + c] += silu_f(lo + bias);
            y[(r0 + 2*p + 1) * 128 + c] += silu_f(hi + bias);
        }
    }
}

// ---------------- edge filter MLP + scatter (hot kernel, f32x2) ----------------
// smem: sw1 6400 | sw2 16384 | sb1 128 | sb2 128 | srbf 3200 | shd 128*66 | scv 64 | sx1 256 | sdst 64
#define SHD_PAD 66
#define FILT_SMEM_FLOATS (6400 + 16384 + 128 + 128 + 3200 + 128*SHD_PAD + 64 + 256 + 64)

__global__ void __launch_bounds__(256, 1)
filter_kernel(const float* __restrict__ w1, const float* __restrict__ b1,
              const float* __restrict__ w2, const float* __restrict__ b2,
              int ntiles)
{
    extern __shared__ float sm[];
    float* sw1  = sm;                      // 50*128
    float* sw2  = sw1 + 6400;              // 128*128
    float* sb1  = sw2 + 16384;             // 128
    float* sb2  = sb1 + 128;               // 128
    float* srbf = sb2 + 128;               // [g][64 edges]
    float* shd  = srbf + 3200;             // [k][66]
    float* scv  = shd + 128 * SHD_PAD;     // 64
    float* sx1  = scv + 64;                // 2 rows x 128
    int*   sdst = (int*)(sx1 + 256);       // 64

    const int tid = threadIdx.x;
    const int cg  = tid & 31;              // channel group (lane)
    const int eg  = tid >> 5;              // edge group (warp)
    const int c0  = cg * 4;                // 4 channels
    const int eb  = eg * 8;                // 8 edges

    for (int idx = tid; idx < 6400;  idx += 256) sw1[idx] = w1[idx];
    for (int idx = tid; idx < 16384; idx += 256) sw2[idx] = w2[idx];
    if (tid < 128) { sb1[tid] = b1[tid]; sb2[tid] = b2[tid]; }
    __syncthreads();

    const float4 b1v = *(const float4*)&sb1[c0];
    const float4 b2v = *(const float4*)&sb2[c0];

    for (int tile = blockIdx.x; tile < ntiles; tile += gridDim.x) {
        const int e0 = tile * 64;
        #pragma unroll 4
        for (int idx = tid; idx < 3200; idx += 256)
            srbf[idx] = g_rbf[tile * 3200 + idx];
        if (tid < 64) { scv[tid] = g_cval[e0 + tid]; sdst[tid] = g_idx[e0 + tid]; }
        sx1[tid] = g_x1[(2 * tile) * 128 + tid];    // rows 2*tile, 2*tile+1
        __syncthreads();

        // ---- GEMM1: [64,50] x [50,128] ----
        ull acc[16];
        #pragma unroll
        for (int p = 0; p < 16; p++) acc[p] = 0ULL;

        #pragma unroll 2
        for (int g = 0; g < NG; g++) {
            const float4 w = *(const float4*)&sw1[g * 128 + c0];
            const ull wp0 = pack2(w.x, w.x);
            const ull wp1 = pack2(w.y, w.y);
            const ull wp2 = pack2(w.z, w.z);
            const ull wp3 = pack2(w.w, w.w);
            const float* rp = &srbf[g * 64 + eb];
            #pragma unroll
            for (int j = 0; j < 4; j++) {
                const ull rj = *(const ull*)(rp + 2 * j);
                acc[0*4 + j] = fma2(rj, wp0, acc[0*4 + j]);
                acc[1*4 + j] = fma2(rj, wp1, acc[1*4 + j]);
                acc[2*4 + j] = fma2(rj, wp2, acc[2*4 + j]);
                acc[3*4 + j] = fma2(rj, wp3, acc[3*4 + j]);
            }
        }

        // silu -> shd[k][e] transposed store
        #pragma unroll
        for (int q = 0; q < 4; q++) {
            const float bq = (q == 0) ? b1v.x : (q == 1) ? b1v.y : (q == 2) ? b1v.z : b1v.w;
            #pragma unroll
            for (int j = 0; j < 4; j++) {
                float lo, hi; unpack2(acc[q*4 + j], lo, hi);
                float2 s;
                s.x = silu_f(lo + bq);
                s.y = silu_f(hi + bq);
                *(float2*)&shd[(c0 + q) * SHD_PAD + eb + 2 * j] = s;
            }
        }
        __syncthreads();

        // ---- GEMM2: [64,128] x [128,128] ----
        #pragma unroll
        for (int p = 0; p < 16; p++) acc[p] = 0ULL;

        #pragma unroll 2
        for (int k = 0; k < 128; k++) {
            const float4 w = *(const float4*)&sw2[k * 128 + c0];
            const ull wp0 = pack2(w.x, w.x);
            const ull wp1 = pack2(w.y, w.y);
            const ull wp2 = pack2(w.z, w.z);
            const ull wp3 = pack2(w.w, w.w);
            const float* hp = &shd[k * SHD_PAD + eb];
            #pragma unroll
            for (int j = 0; j < 4; j++) {
                const ull hj = *(const ull*)(hp + 2 * j);
                acc[0*4 + j] = fma2(hj, wp0, acc[0*4 + j]);
                acc[1*4 + j] = fma2(hj, wp1, acc[1*4 + j]);
                acc[2*4 + j] = fma2(hj, wp2, acc[2*4 + j]);
                acc[3*4 + j] = fma2(hj, wp3, acc[3*4 + j]);
            }
        }

        // ---- epilogue: m = (acc + b2) * cval * x1[src], vector red ----
        const float4 x1v = *(const float4*)&sx1[(eb >= 32 ? 128 : 0) + c0];
        #pragma unroll
        for (int j = 0; j < 4; j++) {
            const int   e   = eb + 2 * j;
            const float cv0 = scv[e];
            const float cv1 = scv[e + 1];
            const int   d0  = sdst[e];
            const int   d1  = sdst[e + 1];
            float m0[4], m1[4];
            #pragma unroll
            for (int q = 0; q < 4; q++) {
                const float bq  = (q == 0) ? b2v.x : (q == 1) ? b2v.y : (q == 2) ? b2v.z : b2v.w;
                const float xq  = (q == 0) ? x1v.x : (q == 1) ? x1v.y : (q == 2) ? x1v.z : x1v.w;
                float lo, hi; unpack2(acc[q*4 + j], lo, hi);
                m0[q] = (lo + bq) * cv0 * xq;
                m1[q] = (hi + bq) * cv1 * xq;
            }
            red_add_v4(&g_agg[d0 * 128 + c0], m0[0], m0[1], m0[2], m0[3]);
            red_add_v4(&g_agg[d1 * 128 + c0], m1[0], m1[1], m1[2], m1[3]);
        }
        __syncthreads();
    }
}

// ---------------- output head + per-graph sum ----------------
#define OUT_SMEM_FLOATS (128*128 + 128*65)

__global__ void out_kernel(const float* __restrict__ ow1, const float* __restrict__ ob1,
                           const float* __restrict__ ow2, const float* __restrict__ ob2,
                           float* __restrict__ out)
{
    extern __shared__ float sm[];
    float* sh = sm;
    float* st = sh + 128*128;
    __shared__ float rsum[256];

    const int g    = blockIdx.x;
    const int tid  = threadIdx.x;
    const int base = g * ATOMS;

    for (int idx = tid; idx < 128 * 128; idx += 256)
        sh[idx] = g_h[base * 128 + idx];
    __syncthreads();

    const int d   = tid & 63;
    const int grp = tid >> 6;
    float acc[32];
    #pragma unroll
    for (int e = 0; e < 32; e++) acc[e] = 0.0f;
    const float* hh = sh + grp * 32 * 128;
    #pragma unroll 2
    for (int k = 0; k < 128; k++) {
        const float w = ow1[k * 64 + d];
        #pragma unroll
        for (int e = 0; e < 32; e++) acc[e] += hh[e * 128 + k] * w;
    }
    const float bb = ob1[d];
    #pragma unroll
    for (int e = 0; e < 32; e++) {
        const float v = acc[e] + bb;
        st[(grp * 32 + e) * 65 + d] = silu_f(v);
    }
    __syncthreads();

    float o = 0.0f;
    if (tid < 128) {
        float s = ob2[0];
        #pragma unroll 4
        for (int dd = 0; dd < 64; dd++) s += st[tid * 65 + dd] * ow2[dd];
        o = s;
    }
    rsum[tid] = o;
    __syncthreads();
    for (int s = 128; s >= 1; s >>= 1) {
        if (tid < s) rsum[tid] += rsum[tid + s];
        __syncthreads();
    }
    if (tid == 0) out[g] = rsum[0];
}

// ---------------- launch ----------------
extern "C" void kernel_launch(void* const* d_in, const int* in_sizes, int n_in,
                              void* d_out, int out_size)
{
    const float* pos   = (const float*)d_in[0];
    const int*   z     = (const int*)  d_in[1];
    const int*   batch = (const int*)  d_in[2];
    const float* emb   = (const float*)d_in[3];
    const float* mw1   = (const float*)d_in[4];
    const float* mb1   = (const float*)d_in[5];
    const float* mw2   = (const float*)d_in[6];
    const float* mb2   = (const float*)d_in[7];
    const float* l1w   = (const float*)d_in[8];
    const float* l1b   = (const float*)d_in[9];
    const float* l2w   = (const float*)d_in[10];
    const float* l2b   = (const float*)d_in[11];
    const float* ow1   = (const float*)d_in[12];
    const float* ob1   = (const float*)d_in[13];
    const float* ow2   = (const float*)d_in[14];
    const float* ob2   = (const float*)d_in[15];
    float* out = (float*)d_out;

    float *hp, *x1p, *aggp;
    cudaGetSymbolAddress((void**)&hp,   g_h);
    cudaGetSymbolAddress((void**)&x1p,  g_x1);
    cudaGetSymbolAddress((void**)&aggp, g_agg);

    cudaFuncSetAttribute(filter_kernel, cudaFuncAttributeMaxDynamicSharedMemorySize,
                         FILT_SMEM_FLOATS * (int)sizeof(float));
    cudaFuncSetAttribute(out_kernel, cudaFuncAttributeMaxDynamicSharedMemorySize,
                         OUT_SMEM_FLOATS * (int)sizeof(float));

    build_graph_kernel<<<NTOT, ATOMS>>>(pos, batch);
    rbf_kernel<<<(EDGES * NG + 255) / 256, 256>>>();
    embed_kernel<<<(NTOT * HID + 255) / 256, 256>>>(z, emb);

    const int ntiles = EDGES / 64;
    for (int l = 0; l < LAYERS; l++) {
        linear_kernel<<<NTOT / 32, 128>>>(hp, l1w + l * HID * FIL, l1b + l * FIL, x1p, 0);
        zero_agg_kernel<<<(NTOT * FIL + 255) / 256, 256>>>();
        filter_kernel<<<148, 256, FILT_SMEM_FLOATS * sizeof(float)>>>(
            mw1 + l * NG * FIL, mb1 + l * FIL,
            mw2 + l * FIL * FIL, mb2 + l * FIL, ntiles);
        linear_kernel<<<NTOT / 32, 128>>>(aggp, l2w + l * FIL * HID, l2b + l * HID, hp, 1);
    }

    out_kernel<<<NUM_G, 256, OUT_SMEM_FLOATS * sizeof(float)>>>(ow1, ob1, ow2, ob2, out);
}

// round 4
// speedup vs baseline: 2.1375x; 1.5154x over previous
#include <cuda_runtime.h>
#include <cuda_bf16.h>
#include <math.h>
#include <stdint.h>

// ---------------- problem constants ----------------
#define NG        50
#define KNB       32
#define NUM_G     64
#define ATOMS     128
#define NTOT      (NUM_G * ATOMS)     // 8192
#define HID       128
#define FIL       128
#define LAYERS    6
#define EDGES     (NTOT * KNB)        // 262144
#define NTILES    (EDGES / 128)       // 2048
#define CUTOFF    10.0f
#define PI_C      3.14159265f

#define INVALID_KEY 0xFFFFFFFFFFFFFFFFULL
typedef unsigned long long ull;

// ---------------- device scratch ----------------
__device__ int   g_idx [EDGES];
__device__ float g_dist[EDGES];
__device__ float g_cval[EDGES];
__device__ float g_h   [NTOT * HID];
__device__ float g_x1  [NTOT * FIL];
__device__ float g_agg [NTOT * FIL];

// ldmatrix-layout bf16 tile images
__device__ unsigned char g_rbf_hi[NTILES * 16384];   // per tile: [128 e][64 k]
__device__ unsigned char g_rbf_lo[NTILES * 16384];
__device__ unsigned char g_w1_hi [LAYERS * 16384];   // [128 n][64 k]
__device__ unsigned char g_w1_lo [LAYERS * 16384];
__device__ unsigned char g_w2_hi [LAYERS * 32768];   // [128 n][128 k]
__device__ unsigned char g_w2_lo [LAYERS * 32768];

__device__ __forceinline__ float silu_f(float v) {
    return v / (1.0f + __expf(-v));
}

// ---------------- packed f32x2 helpers ----------------
__device__ __forceinline__ ull pack2(float x, float y) {
    ull r; asm("mov.b64 %0, {%1,%2};" : "=l"(r) : "f"(x), "f"(y)); return r;
}
__device__ __forceinline__ void unpack2(ull v, float& x, float& y) {
    asm("mov.b64 {%0,%1}, %2;" : "=f"(x), "=f"(y) : "l"(v));
}
__device__ __forceinline__ ull fma2(ull a, ull b, ull c) {
    ull d; asm("fma.rn.f32x2 %0, %1, %2, %3;" : "=l"(d) : "l"(a), "l"(b), "l"(c));
    return d;
}
__device__ __forceinline__ void red_add_v2(float* p, float a, float b) {
    asm volatile("red.global.add.v2.f32 [%0], {%1,%2};"
                 :: "l"(p), "f"(a), "f"(b) : "memory");
}

__device__ __forceinline__ uint32_t smem_u32(const void* p) {
    uint32_t a;
    asm("{ .reg .u64 t; cvta.to.shared.u64 t, %1; cvt.u32.u64 %0, t; }" : "=r"(a) : "l"(p));
    return a;
}

// ---------------- mma.sync / ldmatrix helpers (baseline PTX, sm_80+) ----------------
__device__ __forceinline__ void ldsm4(uint32_t* r, uint32_t addr) {
    asm volatile("ldmatrix.sync.aligned.m8n8.x4.shared.b16 {%0,%1,%2,%3}, [%4];"
                 : "=r"(r[0]), "=r"(r[1]), "=r"(r[2]), "=r"(r[3]) : "r"(addr));
}
__device__ __forceinline__ void mma16816(float* c, const uint32_t* a, uint32_t b0, uint32_t b1) {
    asm volatile("mma.sync.aligned.m16n8k16.row.col.f32.bf16.bf16.f32 "
                 "{%0,%1,%2,%3}, {%4,%5,%6,%7}, {%8,%9}, {%0,%1,%2,%3};"
                 : "+f"(c[0]), "+f"(c[1]), "+f"(c[2]), "+f"(c[3])
                 : "r"(a[0]), "r"(a[1]), "r"(a[2]), "r"(a[3]), "r"(b0), "r"(b1));
}

// swizzled byte offsets for ldmatrix-friendly layouts
// 64-k rows (128B/row): chunk = k>>3 (0..7), xor low3 with row&7
__device__ __forceinline__ uint32_t off1(int r, int k) {
    return (uint32_t)(r * 128 + (((k >> 3) ^ (r & 7)) << 4) + (k & 7) * 2);
}
// 128-k rows (256B/row): chunk = k>>3 (0..15), xor low3 with row&7
__device__ __forceinline__ uint32_t off2(int r, int k) {
    return (uint32_t)(r * 256 + (((k >> 3) ^ (r & 7)) << 4) + (k & 7) * 2);
}

// ---------------- graph build ----------------
__global__ void build_graph_kernel(const float* __restrict__ pos,
                                   const int* __restrict__ batch)
{
    const int i = blockIdx.x;
    const int t = threadIdx.x;
    const int base = (i >> 7) << 7;
    const int j = base + t;

    __shared__ unsigned long long key[ATOMS];
    __shared__ unsigned long long red[ATOMS];

    const float px = pos[3*i], py = pos[3*i+1], pz = pos[3*i+2];
    const float dx = pos[3*j]   - px;
    const float dy = pos[3*j+1] - py;
    const float dz = pos[3*j+2] - pz;
    const float d2 = dx*dx + dy*dy + dz*dz;
    const bool valid = (j != i) && (batch[j] == batch[i]) && (d2 < CUTOFF*CUTOFF);

    key[t] = valid
        ? ((((unsigned long long)__float_as_uint(d2)) << 32) | (unsigned int)j)
        : INVALID_KEY;
    __syncthreads();

    for (int k = 0; k < KNB; k++) {
        red[t] = key[t];
        __syncthreads();
        #pragma unroll
        for (int s = 64; s >= 1; s >>= 1) {
            if (t < s) {
                unsigned long long o = red[t + s];
                if (o < red[t]) red[t] = o;
            }
            __syncthreads();
        }
        const unsigned long long best = red[0];
        if (best != INVALID_KEY && key[t] == best) key[t] = INVALID_KEY;
        if (t == k) {
            const int eo = i * KNB + k;
            if (best != INVALID_KEY) {
                const int   jj = (int)(best & 0xffffffffu);
                const float d  = sqrtf(__uint_as_float((unsigned int)(best >> 32)));
                g_idx[eo]  = jj;
                g_dist[eo] = d;
                const float cv = 0.5f * (cosf(d * (PI_C / CUTOFF)) + 1.0f);
                g_cval[eo] = (d < CUTOFF) ? cv : 0.0f;
            } else {
                g_idx[eo]  = i;
                g_dist[eo] = 1.0f;
                g_cval[eo] = 0.0f;
            }
        }
        __syncthreads();
    }
}

// ---------------- rbf prep: split to bf16 hi/lo ldmatrix-layout tile images ----------------
__global__ void rbf_prep_kernel()
{
    const int id = blockIdx.x * blockDim.x + threadIdx.x;
    if (id >= EDGES * 64) return;
    const int e = id >> 6;
    const int k = id & 63;
    const int tile = e >> 7;
    const int r    = e & 127;
    float val = 0.0f;
    if (k < NG) {
        const float w = CUTOFF / (float)(NG - 1);
        const float t = (g_dist[e] - (float)k * w) / w;
        val = expf(-0.5f * t * t);
    }
    const __nv_bfloat16 hi = __float2bfloat16(val);
    const __nv_bfloat16 lo = __float2bfloat16(val - __bfloat162float(hi));
    const uint32_t o = (uint32_t)tile * 16384u + off1(r, k);
    *(unsigned short*)(g_rbf_hi + o) = __bfloat16_as_ushort(hi);
    *(unsigned short*)(g_rbf_lo + o) = __bfloat16_as_ushort(lo);
}

// ---------------- weight prep ----------------
__global__ void w1_prep_kernel(const float* __restrict__ mw1)
{
    const int id = blockIdx.x * blockDim.x + threadIdx.x;   // LAYERS*128*64
    if (id >= LAYERS * 128 * 64) return;
    const int l = id >> 13;
    const int n = (id >> 6) & 127;
    const int k = id & 63;
    const float val = (k < NG) ? mw1[l * NG * FIL + k * FIL + n] : 0.0f;
    const __nv_bfloat16 hi = __float2bfloat16(val);
    const __nv_bfloat16 lo = __float2bfloat16(val - __bfloat162float(hi));
    const uint32_t o = (uint32_t)l * 16384u + off1(n, k);
    *(unsigned short*)(g_w1_hi + o) = __bfloat16_as_ushort(hi);
    *(unsigned short*)(g_w1_lo + o) = __bfloat16_as_ushort(lo);
}

__global__ void w2_prep_kernel(const float* __restrict__ mw2)
{
    const int id = blockIdx.x * blockDim.x + threadIdx.x;   // LAYERS*128*128
    if (id >= LAYERS * 128 * 128) return;
    const int l = id >> 14;
    const int n = (id >> 7) & 127;
    const int k = id & 127;
    const float val = mw2[l * FIL * FIL + k * FIL + n];
    const __nv_bfloat16 hi = __float2bfloat16(val);
    const __nv_bfloat16 lo = __float2bfloat16(val - __bfloat162float(hi));
    const uint32_t o = (uint32_t)l * 32768u + off2(n, k);
    *(unsigned short*)(g_w2_hi + o) = __bfloat16_as_ushort(hi);
    *(unsigned short*)(g_w2_lo + o) = __bfloat16_as_ushort(lo);
}

// ---------------- embedding ----------------
__global__ void embed_kernel(const int* __restrict__ z, const float* __restrict__ emb)
{
    const int id = blockIdx.x * blockDim.x + threadIdx.x;
    if (id >= NTOT * HID) return;
    const int n = id >> 7;
    const int c = id & 127;
    g_h[id] = emb[z[n] * HID + c];
}

// ---------------- zero agg ----------------
__global__ void zero_agg_kernel()
{
    const int id = blockIdx.x * blockDim.x + threadIdx.x;
    if (id < NTOT * FIL) g_agg[id] = 0.0f;
}

// ---------------- node linear (f32x2, 8 rows/block) ----------------
__global__ void linear_kernel(const float* __restrict__ x,
                              const float* __restrict__ W,
                              const float* __restrict__ b,
                              float* __restrict__ y,
                              int mode)
{
    __shared__ float xs[128 * 8];       // [k][e]
    const int c  = threadIdx.x;
    const int r0 = blockIdx.x * 8;

    #pragma unroll
    for (int e = 0; e < 8; e++)
        xs[c * 8 + e] = x[(r0 + e) * 128 + c];
    __syncthreads();

    ull acc[4];
    #pragma unroll
    for (int p = 0; p < 4; p++) acc[p] = 0ULL;

    #pragma unroll 4
    for (int k = 0; k < 128; k++) {
        const float w = W[k * 128 + c];
        const ull wp = pack2(w, w);
        const float* xp = &xs[k * 8];
        #pragma unroll
        for (int p = 0; p < 4; p++) {
            const ull xv = *(const ull*)(xp + 2 * p);
            acc[p] = fma2(xv, wp, acc[p]);
        }
    }
    const float bias = b[c];
    if (mode == 0) {
        #pragma unroll
        for (int p = 0; p < 4; p++) {
            float lo, hi; unpack2(acc[p], lo, hi);
            y[(r0 + 2*p)     * 128 + c] = lo + bias;
            y[(r0 + 2*p + 1) * 128 + c] = hi + bias;
        }
    } else {
        #pragma unroll
        for (int p = 0; p < 4; p++) {
            float lo, hi; unpack2(acc[p], lo, hi);
            y[(r0 + 2*p)     * 128 + c] += silu_f(lo + bias);
            y[(r0 + 2*p + 1) * 128 + c] += silu_f(hi + bias);
        }
    }
}

// ---------------- tensor-core (mma.sync) filter kernel ----------------
// smem byte offsets (128-aligned base guaranteed by extern __shared__)
#define SO_A1HI 0
#define SO_A1LO 16384
#define SO_A2HI 32768
#define SO_A2LO 65536
#define SO_B1HI 98304
#define SO_B1LO 114688
#define SO_B2HI 131072
#define SO_B2LO 163840
#define SO_AUX  196608
#define AUX_X1P 0                 // 512 floats (4 src rows x 128)
#define AUX_X1Q 2048              // 512 floats
#define AUX_CV  4096              // 128 floats
#define AUX_B1  4608              // 128 floats
#define AUX_DST 5120              // 128 ints
#define FILT_SMEM_BYTES (SO_AUX + 5632)

__global__ void __launch_bounds__(256, 1)
filter_mma_kernel(const float* __restrict__ b1g, const float* __restrict__ b2g,
                  const unsigned char* __restrict__ w1hi, const unsigned char* __restrict__ w1lo,
                  const unsigned char* __restrict__ w2hi, const unsigned char* __restrict__ w2lo)
{
    extern __shared__ unsigned char base[];
    const uint32_t base32 = smem_u32(base);

    const int tid  = threadIdx.x;
    const int wid  = tid >> 5;
    const int lane = tid & 31;
    const int wm   = wid & 3;          // warp m-tile: 32 edges
    const int wn   = wid >> 2;         // warp n-tile: 64 channels
    const int m0w  = wm * 32;
    const int n0w  = wn * 64;

    float* sx1p = (float*)(base + SO_AUX + AUX_X1P);
    float* sx1q = (float*)(base + SO_AUX + AUX_X1Q);
    float* scv  = (float*)(base + SO_AUX + AUX_CV);
    float* sb1  = (float*)(base + SO_AUX + AUX_B1);
    int*   sdst = (int*)  (base + SO_AUX + AUX_DST);

    // resident weight copies
    {
        const uint4* s1h = (const uint4*)w1hi;  const uint4* s1l = (const uint4*)w1lo;
        const uint4* s2h = (const uint4*)w2hi;  const uint4* s2l = (const uint4*)w2lo;
        uint4* d1h = (uint4*)(base + SO_B1HI);  uint4* d1l = (uint4*)(base + SO_B1LO);
        uint4* d2h = (uint4*)(base + SO_B2HI);  uint4* d2l = (uint4*)(base + SO_B2LO);
        for (int i = tid; i < 1024; i += 256) { d1h[i] = s1h[i]; d1l[i] = s1l[i]; }
        for (int i = tid; i < 2048; i += 256) { d2h[i] = s2h[i]; d2l[i] = s2l[i]; }
        if (tid < 128) sb1[tid] = b1g[tid];
    }
    __syncthreads();

    // ldmatrix per-lane row/kb for fragments
    const int lr = lane & 15;          // row within 16
    const int lk = (lane >> 4) * 8;    // k-block 0/8

    for (int tile = blockIdx.x; tile < NTILES; tile += gridDim.x) {
        // ---- stage A1 + aux ----
        {
            const uint4* sh = (const uint4*)(g_rbf_hi + (size_t)tile * 16384);
            const uint4* sl = (const uint4*)(g_rbf_lo + (size_t)tile * 16384);
            uint4* dh = (uint4*)(base + SO_A1HI);
            uint4* dl = (uint4*)(base + SO_A1LO);
            for (int i = tid; i < 1024; i += 256) { dh[i] = sh[i]; dl[i] = sl[i]; }
            const int e0 = tile * 128;
            if (tid < 128) { scv[tid] = g_cval[e0 + tid]; sdst[tid] = g_idx[e0 + tid]; }
            for (int i = tid; i < 512; i += 256) {
                const int jj = i >> 7, c = i & 127;
                const float v = g_x1[(4 * tile + jj) * 128 + c];
                sx1p[i] = v;
                sx1q[i] = v * b2g[c];
            }
        }
        __syncthreads();

        float acc[2][8][4];
        #pragma unroll
        for (int mi = 0; mi < 2; mi++)
            #pragma unroll
            for (int nj = 0; nj < 8; nj++)
                #pragma unroll
                for (int q = 0; q < 4; q++) acc[mi][nj][q] = 0.0f;

        // ---- GEMM1: K=64 over A1 (off1) x B1 (off1) ----
        #pragma unroll
        for (int ks = 0; ks < 4; ks++) {
            const int kb = ks * 16 + lk;
            uint32_t Ah[2][4], Al[2][4];
            #pragma unroll
            for (int mi = 0; mi < 2; mi++) {
                const uint32_t o = off1(m0w + mi * 16 + lr, kb);
                ldsm4(Ah[mi], base32 + SO_A1HI + o);
                ldsm4(Al[mi], base32 + SO_A1LO + o);
            }
            #pragma unroll
            for (int nt = 0; nt < 4; nt++) {
                uint32_t Bh[4], Bl[4];
                const uint32_t o = off1(n0w + nt * 16 + lr, kb);
                ldsm4(Bh, base32 + SO_B1HI + o);
                ldsm4(Bl, base32 + SO_B1LO + o);
                #pragma unroll
                for (int h = 0; h < 2; h++) {
                    const int nj = nt * 2 + h;
                    #pragma unroll
                    for (int mi = 0; mi < 2; mi++) {
                        mma16816(acc[mi][nj], Ah[mi], Bh[h], Bh[2 + h]);
                        mma16816(acc[mi][nj], Ah[mi], Bl[h], Bl[2 + h]);
                        mma16816(acc[mi][nj], Al[mi], Bh[h], Bh[2 + h]);
                    }
                }
            }
        }

        // ---- epilogue1: silu, split, store A2 (off2) ----
        {
            unsigned char* a2h = base + SO_A2HI;
            unsigned char* a2l = base + SO_A2LO;
            const int rbase = m0w + (lane >> 2);
            const int cbase = n0w + (lane & 3) * 2;
            #pragma unroll
            for (int mi = 0; mi < 2; mi++) {
                #pragma unroll
                for (int nj = 0; nj < 8; nj++) {
                    const int col = cbase + nj * 8;
                    const float bb0 = sb1[col], bb1 = sb1[col + 1];
                    #pragma unroll
                    for (int half = 0; half < 2; half++) {
                        const int row = rbase + mi * 16 + half * 8;
                        const float s0 = silu_f(acc[mi][nj][half * 2]     + bb0);
                        const float s1 = silu_f(acc[mi][nj][half * 2 + 1] + bb1);
                        const __nv_bfloat16 h0 = __float2bfloat16(s0);
                        const __nv_bfloat16 h1 = __float2bfloat16(s1);
                        const __nv_bfloat16 l0 = __float2bfloat16(s0 - __bfloat162float(h0));
                        const __nv_bfloat16 l1 = __float2bfloat16(s1 - __bfloat162float(h1));
                        const uint32_t o = off2(row, col);
                        *(uint32_t*)(a2h + o) = (uint32_t)__bfloat16_as_ushort(h0) |
                                                ((uint32_t)__bfloat16_as_ushort(h1) << 16);
                        *(uint32_t*)(a2l + o) = (uint32_t)__bfloat16_as_ushort(l0) |
                                                ((uint32_t)__bfloat16_as_ushort(l1) << 16);
                    }
                }
            }
        }
        __syncthreads();

        #pragma unroll
        for (int mi = 0; mi < 2; mi++)
            #pragma unroll
            for (int nj = 0; nj < 8; nj++)
                #pragma unroll
                for (int q = 0; q < 4; q++) acc[mi][nj][q] = 0.0f;

        // ---- GEMM2: K=128 over A2 (off2) x B2 (off2) ----
        #pragma unroll
        for (int ks = 0; ks < 8; ks++) {
            const int kb = ks * 16 + lk;
            uint32_t Ah[2][4], Al[2][4];
            #pragma unroll
            for (int mi = 0; mi < 2; mi++) {
                const uint32_t o = off2(m0w + mi * 16 + lr, kb);
                ldsm4(Ah[mi], base32 + SO_A2HI + o);
                ldsm4(Al[mi], base32 + SO_A2LO + o);
            }
            #pragma unroll
            for (int nt = 0; nt < 4; nt++) {
                uint32_t Bh[4], Bl[4];
                const uint32_t o = off2(n0w + nt * 16 + lr, kb);
                ldsm4(Bh, base32 + SO_B2HI + o);
                ldsm4(Bl, base32 + SO_B2LO + o);
                #pragma unroll
                for (int h = 0; h < 2; h++) {
                    const int nj = nt * 2 + h;
                    #pragma unroll
                    for (int mi = 0; mi < 2; mi++) {
                        mma16816(acc[mi][nj], Ah[mi], Bh[h], Bh[2 + h]);
                        mma16816(acc[mi][nj], Ah[mi], Bl[h], Bl[2 + h]);
                        mma16816(acc[mi][nj], Al[mi], Bh[h], Bh[2 + h]);
                    }
                }
            }
        }

        // ---- epilogue2: m = cv*(d*x1 + b2*x1), red.v2 ----
        {
            const int rbase = m0w + (lane >> 2);
            const int cbase = n0w + (lane & 3) * 2;
            #pragma unroll
            for (int mi = 0; mi < 2; mi++) {
                #pragma unroll
                for (int half = 0; half < 2; half++) {
                    const int row = rbase + mi * 16 + half * 8;
                    const float cv  = scv[row];
                    const int   dst = sdst[row];
                    const int   j4  = row >> 5;
                    const float* pv = &sx1p[j4 * 128];
                    const float* qv = &sx1q[j4 * 128];
                    float* aggp = &g_agg[dst * 128];
                    #pragma unroll
                    for (int nj = 0; nj < 8; nj++) {
                        const int col = cbase + nj * 8;
                        const float m0 = cv * fmaf(acc[mi][nj][half * 2],     pv[col],     qv[col]);
                        const float m1 = cv * fmaf(acc[mi][nj][half * 2 + 1], pv[col + 1], qv[col + 1]);
                        red_add_v2(aggp + col, m0, m1);
                    }
                }
            }
        }
        __syncthreads();
    }
}

// ---------------- output head + per-graph sum ----------------
#define OUT_SMEM_FLOATS (128*128 + 128*65)

__global__ void out_kernel(const float* __restrict__ ow1, const float* __restrict__ ob1,
                           const float* __restrict__ ow2, const float* __restrict__ ob2,
                           float* __restrict__ out)
{
    extern __shared__ float sm[];
    float* sh = sm;
    float* st = sh + 128*128;
    __shared__ float rsum[256];

    const int g    = blockIdx.x;
    const int tid  = threadIdx.x;
    const int base = g * ATOMS;

    for (int idx = tid; idx < 128 * 128; idx += 256)
        sh[idx] = g_h[base * 128 + idx];
    __syncthreads();

    const int d   = tid & 63;
    const int grp = tid >> 6;
    float acc[32];
    #pragma unroll
    for (int e = 0; e < 32; e++) acc[e] = 0.0f;
    const float* hh = sh + grp * 32 * 128;
    #pragma unroll 2
    for (int k = 0; k < 128; k++) {
        const float w = ow1[k * 64 + d];
        #pragma unroll
        for (int e = 0; e < 32; e++) acc[e] += hh[e * 128 + k] * w;
    }
    const float bb = ob1[d];
    #pragma unroll
    for (int e = 0; e < 32; e++) {
        const float v = acc[e] + bb;
        st[(grp * 32 + e) * 65 + d] = silu_f(v);
    }
    __syncthreads();

    float o = 0.0f;
    if (tid < 128) {
        float s = ob2[0];
        #pragma unroll 4
        for (int dd = 0; dd < 64; dd++) s += st[tid * 65 + dd] * ow2[dd];
        o = s;
    }
    rsum[tid] = o;
    __syncthreads();
    for (int s = 128; s >= 1; s >>= 1) {
        if (tid < s) rsum[tid] += rsum[tid + s];
        __syncthreads();
    }
    if (tid == 0) out[g] = rsum[0];
}

// ---------------- launch ----------------
extern "C" void kernel_launch(void* const* d_in, const int* in_sizes, int n_in,
                              void* d_out, int out_size)
{
    const float* pos   = (const float*)d_in[0];
    const int*   z     = (const int*)  d_in[1];
    const int*   batch = (const int*)  d_in[2];
    const float* emb   = (const float*)d_in[3];
    const float* mw1   = (const float*)d_in[4];
    const float* mb1   = (const float*)d_in[5];
    const float* mw2   = (const float*)d_in[6];
    const float* mb2   = (const float*)d_in[7];
    const float* l1w   = (const float*)d_in[8];
    const float* l1b   = (const float*)d_in[9];
    const float* l2w   = (const float*)d_in[10];
    const float* l2b   = (const float*)d_in[11];
    const float* ow1   = (const float*)d_in[12];
    const float* ob1   = (const float*)d_in[13];
    const float* ow2   = (const float*)d_in[14];
    const float* ob2   = (const float*)d_in[15];
    float* out = (float*)d_out;

    float *hp, *x1p, *aggp;
    cudaGetSymbolAddress((void**)&hp,   g_h);
    cudaGetSymbolAddress((void**)&x1p,  g_x1);
    cudaGetSymbolAddress((void**)&aggp, g_agg);
    unsigned char *w1h, *w1l, *w2h, *w2l;
    cudaGetSymbolAddress((void**)&w1h, g_w1_hi);
    cudaGetSymbolAddress((void**)&w1l, g_w1_lo);
    cudaGetSymbolAddress((void**)&w2h, g_w2_hi);
    cudaGetSymbolAddress((void**)&w2l, g_w2_lo);

    cudaFuncSetAttribute(filter_mma_kernel, cudaFuncAttributeMaxDynamicSharedMemorySize,
                         FILT_SMEM_BYTES);
    cudaFuncSetAttribute(out_kernel, cudaFuncAttributeMaxDynamicSharedMemorySize,
                         OUT_SMEM_FLOATS * (int)sizeof(float));

    build_graph_kernel<<<NTOT, ATOMS>>>(pos, batch);
    rbf_prep_kernel<<<(EDGES * 64) / 256, 256>>>();
    w1_prep_kernel<<<(LAYERS * 128 * 64 + 255) / 256, 256>>>(mw1);
    w2_prep_kernel<<<(LAYERS * 128 * 128 + 255) / 256, 256>>>(mw2);
    embed_kernel<<<(NTOT * HID + 255) / 256, 256>>>(z, emb);

    for (int l = 0; l < LAYERS; l++) {
        linear_kernel<<<NTOT / 8, 128>>>(hp, l1w + l * HID * FIL, l1b + l * FIL, x1p, 0);
        zero_agg_kernel<<<(NTOT * FIL + 255) / 256, 256>>>();
        filter_mma_kernel<<<148, 256, FILT_SMEM_BYTES>>>(
            mb1 + l * FIL, mb2 + l * FIL,
            w1h + l * 16384, w1l + l * 16384,
            w2h + l * 32768, w2l + l * 32768);
        linear_kernel<<<NTOT / 8, 128>>>(aggp, l2w + l * FIL * HID, l2b + l * HID, hp, 1);
    }

    out_kernel<<<NUM_G, 256, OUT_SMEM_FLOATS * sizeof(float)>>>(ow1, ob1, ow2, ob2, out);
}